// round 3
// baseline (speedup 1.0000x reference)
#include <cuda_runtime.h>
#include <math.h>

#define B_ 8
#define CIN 256
#define NPIX 16384          // 128*128
#define CO_TOTAL 512

// ---------------- scratch (__device__ globals; no allocation allowed) ----------------
__device__ __align__(16) float g_h[(size_t)CO_TOTAL * B_ * NPIX];   // [co][b][pix], co<256 damage head
__device__ float g_gn_sum[128];     // [head(2)][b(8)][group(8)]
__device__ float g_gn_sum2[128];
__device__ float g_gn_mu[128];
__device__ float g_gn_rstd[128];
__device__ float g_mean_sum[32];    // [b][c(4)]
__device__ int   g_cnt[8];
__device__ unsigned g_keys[8][4][NPIX];
__device__ float g_topk_sum[32];

// order-preserving float <-> uint key
__device__ __forceinline__ unsigned f2key(float f) {
    unsigned u = __float_as_uint(f);
    return (u & 0x80000000u) ? ~u : (u | 0x80000000u);
}
__device__ __forceinline__ float key2f(unsigned k) {
    return (k & 0x80000000u) ? __uint_as_float(k & 0x7fffffffu) : __uint_as_float(~k);
}

__global__ void zero_kernel() {
    int i = threadIdx.x;
    if (i < 128) { g_gn_sum[i] = 0.f; g_gn_sum2[i] = 0.f; }
    if (i < 32)  g_mean_sum[i] = 0.f;
    if (i < 8)   g_cnt[i] = 0;
}

// ---------------- fused conv3x3 for both heads + GN stats ----------------
// grid = (8 cout-blocks of 64, 512 tiles = 8b * 8ty * 8tx), block = 256 threads
// thread: 4 pixels in a row (px..px+3) x 16 couts -> 64 accumulators
#define SIN_PITCH 21
#define SMEM_FLOATS (16*18*SIN_PITCH + 64*16*12)

__global__ __launch_bounds__(256, 2) void conv_kernel(
    const float* __restrict__ fmap,
    const float* __restrict__ dw1,
    const float* __restrict__ sw1)
{
    extern __shared__ float sm[];
    float* s_in = sm;                      // [16][18][21]
    float* s_w  = sm + 16*18*SIN_PITCH;    // [64][16][12] (taps padded 9->12)
    __shared__ float s_gs[2], s_gs2[2];

    int cb = blockIdx.x;                   // cout block (0..7) -> couts [cb*64, cb*64+64)
    int tileId = blockIdx.y;               // 0..511
    int b  = tileId >> 6;
    int ty = (tileId >> 3) & 7;
    int tx = tileId & 7;
    int y0 = ty * 16, x0 = tx * 16;
    int coBase = cb * 64;

    int tid = threadIdx.x;
    int pt  = tid & 63;                    // pixel-thread 0..63
    int cg  = tid >> 6;                    // cout group 0..3 (16 couts each)
    int py  = pt >> 2;                     // row in tile 0..15
    int px  = (pt & 3) * 4;                // col base 0,4,8,12

    const float* wsrc = (cb < 4) ? (dw1 + cb * 64 * 2304)
                                 : (sw1 + (cb - 4) * 64 * 2304);
    const float* fbase = fmap + (size_t)b * CIN * NPIX;

    float acc[4][16];
#pragma unroll
    for (int p = 0; p < 4; ++p)
#pragma unroll
        for (int j = 0; j < 16; ++j) acc[p][j] = 0.f;

    if (tid < 2) { s_gs[tid] = 0.f; s_gs2[tid] = 0.f; }

    for (int ci0 = 0; ci0 < CIN; ci0 += 16) {
        // load 16-channel 18x18 input halo tile
        for (int i = tid; i < 16*18*18; i += 256) {
            int ci = i / 324;
            int r  = i - ci * 324;
            int iy = r / 18;
            int ix = r - iy * 18;
            int gy = y0 + iy - 1;
            int gx = x0 + ix - 1;
            float v = 0.f;
            if ((unsigned)gy < 128u && (unsigned)gx < 128u)
                v = fbase[(ci0 + ci) * NPIX + gy * 128 + gx];
            s_in[ci * (18*SIN_PITCH) + iy * SIN_PITCH + ix] = v;
        }
        // load 64x16x9 weights (padded stride 12 for LDS.128)
        for (int i = tid; i < 64*16*9; i += 256) {
            int co  = i / 144;
            int r   = i - co * 144;
            int ci  = r / 9;
            int tap = r - ci * 9;
            s_w[(co * 16 + ci) * 12 + tap] = wsrc[co * 2304 + (ci0 + ci) * 9 + tap];
        }
        __syncthreads();

#pragma unroll 1
        for (int ci = 0; ci < 16; ++ci) {
            float iv[3][6];
#pragma unroll
            for (int r = 0; r < 3; ++r)
#pragma unroll
                for (int c = 0; c < 6; ++c)
                    iv[r][c] = s_in[ci * (18*SIN_PITCH) + (py + r) * SIN_PITCH + (px + c)];
#pragma unroll
            for (int j = 0; j < 16; ++j) {
                const float* wp = &s_w[((cg * 16 + j) * 16 + ci) * 12];
                float4 w0 = *(const float4*)wp;        // taps 0..3
                float4 w1 = *(const float4*)(wp + 4);  // taps 4..7
                float  w8 = wp[8];                     // tap 8
#pragma unroll
                for (int p = 0; p < 4; ++p) {
                    float s = acc[p][j];
                    s += w0.x * iv[0][p + 0];
                    s += w0.y * iv[0][p + 1];
                    s += w0.z * iv[0][p + 2];
                    s += w0.w * iv[1][p + 0];
                    s += w1.x * iv[1][p + 1];
                    s += w1.y * iv[1][p + 2];
                    s += w1.z * iv[2][p + 0];
                    s += w1.w * iv[2][p + 1];
                    s += w8  * iv[2][p + 2];
                    acc[p][j] = s;
                }
            }
        }
        __syncthreads();
    }

    // GroupNorm partial stats: thread's 16 couts lie fully inside one 32-ch group
    float s = 0.f, s2 = 0.f;
#pragma unroll
    for (int p = 0; p < 4; ++p)
#pragma unroll
        for (int j = 0; j < 16; ++j) { float v = acc[p][j]; s += v; s2 += v * v; }
    atomicAdd(&s_gs[cg >> 1], s);
    atomicAdd(&s_gs2[cg >> 1], s2);
    __syncthreads();
    if (tid < 2) {
        int gco = coBase + tid * 32;
        int idx = ((gco >> 8) * 8 + b) * 8 + ((gco >> 5) & 7);   // [head][b][group]
        atomicAdd(&g_gn_sum[idx],  s_gs[tid]);
        atomicAdd(&g_gn_sum2[idx], s_gs2[tid]);
    }

    // store h (float4, coalesced)
#pragma unroll
    for (int j = 0; j < 16; ++j) {
        int co = coBase + cg * 16 + j;
        float4 v = make_float4(acc[0][j], acc[1][j], acc[2][j], acc[3][j]);
        *(float4*)&g_h[(co * B_ + b) * NPIX + (y0 + py) * 128 + (x0 + px)] = v;
    }
}

__global__ void gn_finalize() {
    int i = threadIdx.x;
    if (i < 128) {
        const float N = 32.f * 16384.f;
        float mu  = g_gn_sum[i] / N;
        float var = g_gn_sum2[i] / N - mu * mu;
        g_gn_mu[i]   = mu;
        g_gn_rstd[i] = rsqrtf(var + 1e-5f);
    }
}

// ---------------- GN affine + GELU + conv1x1 + decode + masked-mean partials ----------------
__global__ __launch_bounds__(256) void epilogue_kernel(
    const float* __restrict__ mask,
    const float* __restrict__ dgs, const float* __restrict__ dgb,
    const float* __restrict__ dw2, const float* __restrict__ db2,
    const float* __restrict__ sgs, const float* __restrict__ sgb,
    const float* __restrict__ sw2, const float* __restrict__ sb2,
    float* __restrict__ out)
{
    __shared__ float sa0[256], sb0[256], swd[256];
    __shared__ float sa1[256], sb1[256], sws0[256], sws1[256];
    __shared__ float s_msum[4];
    __shared__ int s_mcnt;

    int tid = threadIdx.x;
    int id  = blockIdx.x * 256 + tid;      // global pixel id over B*NPIX
    int b   = id >> 14;
    int pix = id & 16383;

    if (tid < 4) s_msum[tid] = 0.f;
    if (tid == 0) s_mcnt = 0;

    {   // fold GN affine into per-channel (a, b): v = h*a + b   (b fixed per block)
        int c = tid;
        int g = c >> 5;
        float mu0 = g_gn_mu[b * 8 + g],      rs0 = g_gn_rstd[b * 8 + g];
        float a0  = rs0 * dgs[c];
        sa0[c] = a0; sb0[c] = dgb[c] - mu0 * a0; swd[c] = dw2[c];
        float mu1 = g_gn_mu[64 + b * 8 + g], rs1 = g_gn_rstd[64 + b * 8 + g];
        float a1  = rs1 * sgs[c];
        sa1[c] = a1; sb1[c] = sgb[c] - mu1 * a1; sws0[c] = sw2[c]; sws1[c] = sw2[256 + c];
    }
    __syncthreads();

    const float inv_sqrt2 = 0.70710678118654752440f;
    float accd = db2[0];
    const float* hp0 = g_h + b * NPIX + pix;
#pragma unroll 8
    for (int c = 0; c < 256; ++c) {
        float hv = hp0[c * (B_ * NPIX)];
        float v  = hv * sa0[c] + sb0[c];
        float ge = 0.5f * v * (1.f + erff(v * inv_sqrt2));
        accd += swd[c] * ge;
    }
    float acc0 = sb2[0], acc1 = sb2[1];
    const float* hp1 = g_h + (256 * B_ + b) * NPIX + pix;
#pragma unroll 8
    for (int c = 0; c < 256; ++c) {
        float hv = hp1[c * (B_ * NPIX)];
        float v  = hv * sa1[c] + sb1[c];
        float ge = 0.5f * v * (1.f + erff(v * inv_sqrt2));
        acc0 += sws0[c] * ge;
        acc1 += sws1[c] * ge;
    }

    // CORN decode + pixel distribution
    float p  = 1.f / (1.f + expf(-accd));
    float t0 = 1.f / (1.f + expf(-acc0));
    float t1 = t0 * (1.f / (1.f + expf(-acc1)));
    float e0 = 1.f - t0, e1 = t0 - t1, e2 = t1;
    e0 = fmaxf(e0, 1e-8f); e1 = fmaxf(e1, 1e-8f); e2 = fmaxf(e2, 1e-8f);
    float den = fmaxf(e0 + e1 + e2, 1e-8f);
    float sv0 = e0 / den, sv1 = e1 / den, sv2 = e2 / den;

    float q0 = 1.f - p, q1 = p * sv0, q2 = p * sv1, q3 = p * sv2;
    q0 = fmaxf(q0, 1e-8f); q1 = fmaxf(q1, 1e-8f); q2 = fmaxf(q2, 1e-8f); q3 = fmaxf(q3, 1e-8f);
    float dq = fmaxf(q0 + q1 + q2 + q3, 1e-8f);
    q0 /= dq; q1 /= dq; q2 /= dq; q3 /= dq;

    int am = 0; float mv = sv0;
    if (sv1 > mv) { am = 1; mv = sv1; }
    if (sv2 > mv) { am = 2; mv = sv2; }
    int pred = (p >= 0.5f) ? (am + 1) : 0;

    // outputs (flattened tuple order)
    out[id] = accd;                                          // dmg_logit
    out[131072 + (b * 2 + 0) * 16384 + pix] = acc0;          // corn_logits
    out[131072 + (b * 2 + 1) * 16384 + pix] = acc1;
    int pb = 393216 + b * 4 * 16384 + pix;                   // pix
    out[pb            ] = q0;
    out[pb + 16384    ] = q1;
    out[pb + 2 * 16384] = q2;
    out[pb + 3 * 16384] = q3;
    out[917504 + id] = (float)pred;                          // pred_labels

    bool valid = mask[id] > 0.5f;
    g_keys[b][0][pix] = valid ? f2key(q0) : 0u;
    g_keys[b][1][pix] = valid ? f2key(q1) : 0u;
    g_keys[b][2][pix] = valid ? f2key(q2) : 0u;
    g_keys[b][3][pix] = valid ? f2key(q3) : 0u;

    __syncthreads();
    if (valid) {
        atomicAdd(&s_msum[0], q0);
        atomicAdd(&s_msum[1], q1);
        atomicAdd(&s_msum[2], q2);
        atomicAdd(&s_msum[3], q3);
        atomicAdd(&s_mcnt, 1);
    }
    __syncthreads();
    if (tid < 4) atomicAdd(&g_mean_sum[b * 4 + tid], s_msum[tid]);
    if (tid == 4) atomicAdd(&g_cnt[b], s_mcnt);
}

// ---------------- exact top-k sum via MSB-first radix select ----------------
__global__ void topk_kernel() {
    __shared__ unsigned h_cnt[256];
    __shared__ float h_sum[256];
    __shared__ unsigned sh_prefix; __shared__ int sh_krem; __shared__ float sh_sum;

    int b = blockIdx.x >> 2;
    int c = blockIdx.x & 3;
    int tid = threadIdx.x;
    int cnt = g_cnt[b];
    int k = (int)rintf((float)cnt * 0.2f);
    int hi = cnt > 1 ? cnt : 1;
    if (k < 1) k = 1;
    if (k > hi) k = hi;

    const unsigned* keys = g_keys[b][c];
    unsigned prefix = 0;
    int krem = k;
    float sum = 0.f;

    for (int pass = 3; pass >= 0; --pass) {
        for (int i = tid; i < 256; i += 256) { h_cnt[i] = 0u; h_sum[i] = 0.f; }
        __syncthreads();
        int shift = pass * 8;
        unsigned pmask = (pass == 3) ? 0u : (0xFFFFFFFFu << (8 * (pass + 1)));
        for (int i = tid; i < NPIX; i += 256) {
            unsigned u = keys[i];
            if (u != 0u && (u & pmask) == prefix) {
                unsigned d = (u >> shift) & 255u;
                atomicAdd(&h_cnt[d], 1u);
                atomicAdd(&h_sum[d], key2f(u));
            }
        }
        __syncthreads();
        if (tid == 0) {
            int cum = 0; float ls = sum; int d;
            for (d = 255; d > 0; --d) {
                int hc = (int)h_cnt[d];
                if (cum + hc >= krem) break;
                cum += hc; ls += h_sum[d];
            }
            sh_prefix = prefix | ((unsigned)d << shift);
            sh_krem = krem - cum;
            sh_sum = ls;
        }
        __syncthreads();
        prefix = sh_prefix; krem = sh_krem; sum = sh_sum;
        __syncthreads();
    }
    if (tid == 0)
        g_topk_sum[b * 4 + c] = sum + (float)krem * key2f(prefix);
}

// ---------------- final small aggregations ----------------
__global__ void finalize_kernel(float* __restrict__ out) {
    int b = threadIdx.x;
    if (b >= 8) return;
    int cnt = g_cnt[b];
    float mean[4], topk[4];
    if (cnt == 0) {
#pragma unroll
        for (int c = 0; c < 4; ++c) { mean[c] = 0.25f; topk[c] = 0.25f; }
    } else {
        float dn = (float)cnt;
#pragma unroll
        for (int c = 0; c < 4; ++c) mean[c] = g_mean_sum[b * 4 + c] / dn;
        int k = (int)rintf((float)cnt * 0.2f);
        if (k < 1) k = 1;
        if (k > cnt) k = cnt;
#pragma unroll
        for (int c = 0; c < 4; ++c) topk[c] = g_topk_sum[b * 4 + c] / (float)k;
    }
    float s = 0.f;
#pragma unroll
    for (int c = 0; c < 4; ++c) { mean[c] = fmaxf(mean[c], 1e-8f); s += mean[c]; }
    s = fmaxf(s, 1e-8f);
#pragma unroll
    for (int c = 0; c < 4; ++c) mean[c] /= s;
    s = 0.f;
#pragma unroll
    for (int c = 0; c < 4; ++c) { topk[c] = fmaxf(topk[c], 1e-8f); s += topk[c]; }
    s = fmaxf(s, 1e-8f);
#pragma unroll
    for (int c = 0; c < 4; ++c) topk[c] /= s;
    float agg[4]; s = 0.f;
#pragma unroll
    for (int c = 0; c < 4; ++c) { agg[c] = fmaxf(0.7f * mean[c] + 0.3f * topk[c], 1e-8f); s += agg[c]; }
    s = fmaxf(s, 1e-8f);
#pragma unroll
    for (int c = 0; c < 4; ++c) agg[c] /= s;
    int am = 0;
#pragma unroll
    for (int c = 1; c < 4; ++c) if (agg[c] > agg[am]) am = c;

#pragma unroll
    for (int c = 0; c < 4; ++c) {
        out[1048576 + b * 4 + c] = mean[c];
        out[1048608 + b * 4 + c] = topk[c];
        out[1048640 + b * 4 + c] = agg[c];
    }
    out[1048672 + b] = (float)am;
}

// ---------------- launch ----------------
extern "C" void kernel_launch(void* const* d_in, const int* in_sizes, int n_in,
                              void* d_out, int out_size) {
    const float* fmap = (const float*)d_in[0];
    const float* mask = (const float*)d_in[1];
    const float* dw1  = (const float*)d_in[2];
    const float* dgs  = (const float*)d_in[3];
    const float* dgb  = (const float*)d_in[4];
    const float* dw2  = (const float*)d_in[5];
    const float* db2  = (const float*)d_in[6];
    const float* sw1  = (const float*)d_in[7];
    const float* sgs  = (const float*)d_in[8];
    const float* sgb  = (const float*)d_in[9];
    const float* sw2  = (const float*)d_in[10];
    const float* sb2  = (const float*)d_in[11];
    float* out = (float*)d_out;

    const int smem_bytes = SMEM_FLOATS * sizeof(float);   // 73344
    cudaFuncSetAttribute(conv_kernel, cudaFuncAttributeMaxDynamicSharedMemorySize, smem_bytes);

    zero_kernel<<<1, 128>>>();
    conv_kernel<<<dim3(8, 512), 256, smem_bytes>>>(fmap, dw1, sw1);
    gn_finalize<<<1, 128>>>();
    epilogue_kernel<<<512, 256>>>(mask, dgs, dgb, dw2, db2, sgs, sgb, sw2, sb2, out);
    topk_kernel<<<32, 256>>>();
    finalize_kernel<<<1, 8>>>(out);
}